// round 7
// baseline (speedup 1.0000x reference)
#include <cuda_runtime.h>

#define N_NODES 65536
#define N_EDGES 1048576
#define NOUT 512
#define NBLK  444
#define NFOLD 128
#define NGB   (NBLK - NFOLD)      // 316 graph blocks
#define NTHR  256
#define GT    (NGB * NTHR)        // 80896 graph threads

// ---------------- device scratch (no allocation allowed) ----------------
__device__ float    g_deg[N_NODES];
__device__ float    g_dinv[N_NODES];
__device__ float4   g_xs[N_NODES];
__device__ float4   g_agg1[N_NODES];
__device__ float4   g_agg2[N_NODES];
__device__ float    g_M4[1024 * NOUT];    // folded [W2;b2]@W3 : [1024][512]
__device__ int2     g_eidx[N_EDGES];
__device__ int      g_is64;
__device__ unsigned g_bar[8];

__device__ __forceinline__ void red_add_v3(float* a, float x, float y, float z) {
    asm volatile("red.global.add.v4.f32 [%0], {%1, %2, %3, %4};"
                 :: "l"(a), "f"(x), "f"(y), "f"(z), "f"(0.0f) : "memory");
}
__device__ __forceinline__ void red_add_v4f(float* a, float4 v) {
    asm volatile("red.global.add.v4.f32 [%0], {%1, %2, %3, %4};"
                 :: "l"(a), "f"(v.x), "f"(v.y), "f"(v.z), "f"(v.w) : "memory");
}

// software grid barrier (counters zeroed by k_reset each call)
__device__ __forceinline__ void bar_sync(int id, unsigned n) {
    __syncthreads();
    __threadfence();
    if (threadIdx.x == 0) {
        atomicAdd(&g_bar[id], 1u);
        while (*((volatile unsigned*)&g_bar[id]) < n) { }
    }
    __syncthreads();
    __threadfence();   // gpu-scope: invalidates L1 so post-barrier loads are fresh
}

__global__ void k_reset() {
    if (threadIdx.x < 8) g_bar[threadIdx.x] = 0u;
}

__device__ __forceinline__ int edge_src(const void* ei, int e) {
    if (g_is64) return (int)((const long long*)ei)[e];
    return ((const int*)ei)[e];
}
__device__ __forceinline__ int edge_dst(const void* ei, int e) {
    if (g_is64) return (int)((const long long*)ei)[N_EDGES + e];
    return ((const int*)ei)[N_EDGES + e];
}

__global__ void __launch_bounds__(NTHR, 3)
k_all(const float* __restrict__ nodes, const void* __restrict__ ei,
      const float* __restrict__ W1, const float* __restrict__ b1,
      const float* __restrict__ W2, const float* __restrict__ b2,
      const float2* __restrict__ W3, const float* __restrict__ b3,
      float* __restrict__ out) {
    __shared__ float As[16][65];
    __shared__ float Bs[16][64];
    __shared__ float sw[4][128];

    const int bid = blockIdx.x;
    const int t   = threadIdx.x;

    if (bid < NFOLD) {
        // ---------- fold: M4[(4p+c),n] = sum_j [W2;b2][c][j] * W3[128p+j][n] ----------
        // independent of the graph pipeline; overlaps with it, meets at bar 5.
        for (int p = bid; p < 256; p += NFOLD) {
            if (t < 128) {
                sw[0][t] = W2[t];
                sw[1][t] = W2[128 + t];
                sw[2][t] = W2[256 + t];
                sw[3][t] = b2[t];
            }
            __syncthreads();
            const float2* base = W3 + (size_t)p * 128 * 256 + t;   // row p*128+j, f2-col t
            float2 a0 = make_float2(0.f, 0.f), a1 = a0, a2 = a0, a3 = a0;
#pragma unroll 8
            for (int j = 0; j < 128; j++) {
                float2 w = __ldg(base + (size_t)j * 256);
                float c0 = sw[0][j], c1 = sw[1][j], c2 = sw[2][j], c3 = sw[3][j];
                a0.x += w.x * c0; a0.y += w.y * c0;
                a1.x += w.x * c1; a1.y += w.y * c1;
                a2.x += w.x * c2; a2.y += w.y * c2;
                a3.x += w.x * c3; a3.y += w.y * c3;
            }
            float2* M = (float2*)g_M4;
            int rb = p * 4;
            M[(size_t)(rb + 0) * 256 + t] = a0;
            M[(size_t)(rb + 1) * 256 + t] = a1;
            M[(size_t)(rb + 2) * 256 + t] = a2;
            M[(size_t)(rb + 3) * 256 + t] = a3;
            __syncthreads();
        }
    } else {
        // ---------- graph pipeline on NGB blocks ----------
        const int gtid = (bid - NFOLD) * NTHR + t;

        // P0: init
        for (int i = gtid; i < N_NODES; i += GT) {
            g_deg[i]  = 0.f;
            g_agg1[i] = make_float4(0.f, 0.f, 0.f, 0.f);
            g_agg2[i] = make_float4(0.f, 0.f, 0.f, 0.f);
        }
        for (int i = gtid; i < 256 * NOUT; i += GT) out[i] = 0.f;
        if (gtid == 0) {
            const unsigned* raw = (const unsigned*)ei;
            int is64 = 1;
            for (int k = 0; k < 64; k++)
                if (raw[2 * k + 1] != 0u) { is64 = 0; break; }
            g_is64 = is64;
        }
        bar_sync(0, NGB);

        // P1: degree + index conversion
        for (int e = gtid; e < N_EDGES; e += GT) {
            int s = edge_src(ei, e);
            int d = edge_dst(ei, e);
            g_eidx[e] = make_int2(s, d);
            atomicAdd(&g_deg[d], 1.0f);
        }
        bar_sync(1, NGB);

        // P2: dinv + scaled features
        for (int i = gtid; i < N_NODES; i += GT) {
            float dv = rsqrtf(g_deg[i] + 1.0f);
            g_dinv[i] = dv;
            float x0 = nodes[3 * i + 0];
            float x1 = nodes[3 * i + 1];
            float x2 = nodes[3 * i + 2];
            g_xs[i] = make_float4(x0 * dv, x1 * dv, x2 * dv, 0.f);
        }
        bar_sync(2, NGB);

        // P3: scatter layer 1
#pragma unroll 4
        for (int e = gtid; e < N_EDGES; e += GT) {
            int2 sd = __ldg(&g_eidx[e]);
            float4 v = __ldg(&g_xs[sd.x]);
            red_add_v3((float*)&g_agg1[sd.y], v.x, v.y, v.z);
        }
        bar_sync(3, NGB);

        // P4: lin1 + leaky relu + prescale for layer 2
        for (int i = gtid; i < N_NODES; i += GT) {
            float dv = g_dinv[i];
            float4 a = g_agg1[i];
            float4 s = g_xs[i];
            float t0 = dv * (a.x + s.x);
            float t1 = dv * (a.y + s.y);
            float t2 = dv * (a.z + s.z);
            float h0 = t0 * __ldg(&W1[0]) + t1 * __ldg(&W1[3]) + t2 * __ldg(&W1[6]) + __ldg(&b1[0]);
            float h1 = t0 * __ldg(&W1[1]) + t1 * __ldg(&W1[4]) + t2 * __ldg(&W1[7]) + __ldg(&b1[1]);
            float h2 = t0 * __ldg(&W1[2]) + t1 * __ldg(&W1[5]) + t2 * __ldg(&W1[8]) + __ldg(&b1[2]);
            h0 = (h0 >= 0.f) ? h0 : 0.1f * h0;
            h1 = (h1 >= 0.f) ? h1 : 0.1f * h1;
            h2 = (h2 >= 0.f) ? h2 : 0.1f * h2;
            g_xs[i] = make_float4(h0 * dv, h1 * dv, h2 * dv, 0.f);
        }
        bar_sync(4, NGB);

        // P5: scatter layer 2
#pragma unroll 4
        for (int e = gtid; e < N_EDGES; e += GT) {
            int2 sd = __ldg(&g_eidx[e]);
            float4 v = __ldg(&g_xs[sd.x]);
            red_add_v3((float*)&g_agg2[sd.y], v.x, v.y, v.z);
        }
    }

    // ---------- join: fold done AND graph done ----------
    bar_sync(5, NBLK);

    // ---------- GEMM: out[256,512] = U[256,1024] @ M4[1024,512] + b3 ----------
    // U computed on the fly from agg2/xs/dinv. 512 virtual tiles (4 m, 8 n, 16 k-splits).
    for (int vt = bid; vt < 512; vt += NBLK) {
        int m0 = (vt & 3) * 64;
        int n0 = ((vt >> 2) & 7) * 64;
        int k0 = (vt >> 5) * 64;
        int tx = t & 15;           // n quad
        int ty = t >> 4;           // m quad

        float acc[4][4];
#pragma unroll
        for (int i = 0; i < 4; i++)
#pragma unroll
            for (int j = 0; j < 4; j++) acc[i][j] = 0.f;

        for (int kb = 0; kb < 64; kb += 16) {
            {
                int m = t >> 2, kq = t & 3;
                int node = (m0 + m) * 256 + ((k0 + kb) >> 2) + kq;
                float dv = __ldg(&g_dinv[node]);
                float4 a = __ldg(&g_agg2[node]);
                float4 s = __ldg(&g_xs[node]);
                As[kq * 4 + 0][m] = dv * (a.x + s.x);
                As[kq * 4 + 1][m] = dv * (a.y + s.y);
                As[kq * 4 + 2][m] = dv * (a.z + s.z);
                As[kq * 4 + 3][m] = 1.0f;
                int kk = t >> 4, nq = t & 15;
                float4 bv = *(const float4*)&g_M4[(size_t)(k0 + kb + kk) * 512 + n0 + nq * 4];
                *(float4*)&Bs[kk][nq * 4] = bv;
            }
            __syncthreads();
#pragma unroll
            for (int kk = 0; kk < 16; kk++) {
                float a0 = As[kk][ty * 4 + 0];
                float a1 = As[kk][ty * 4 + 1];
                float a2 = As[kk][ty * 4 + 2];
                float a3 = As[kk][ty * 4 + 3];
                float4 bv = *(const float4*)&Bs[kk][tx * 4];
                acc[0][0] += a0 * bv.x; acc[0][1] += a0 * bv.y; acc[0][2] += a0 * bv.z; acc[0][3] += a0 * bv.w;
                acc[1][0] += a1 * bv.x; acc[1][1] += a1 * bv.y; acc[1][2] += a1 * bv.z; acc[1][3] += a1 * bv.w;
                acc[2][0] += a2 * bv.x; acc[2][1] += a2 * bv.y; acc[2][2] += a2 * bv.z; acc[2][3] += a2 * bv.w;
                acc[3][0] += a3 * bv.x; acc[3][1] += a3 * bv.y; acc[3][2] += a3 * bv.z; acc[3][3] += a3 * bv.w;
            }
            __syncthreads();
        }

#pragma unroll
        for (int i = 0; i < 4; i++) {
            int m = m0 + ty * 4 + i;
            int n = n0 + tx * 4;
            float4 v = make_float4(acc[i][0], acc[i][1], acc[i][2], acc[i][3]);
            if (k0 == 0) {
                v.x += __ldg(&b3[n + 0]);
                v.y += __ldg(&b3[n + 1]);
                v.z += __ldg(&b3[n + 2]);
                v.w += __ldg(&b3[n + 3]);
            }
            red_add_v4f(&out[(size_t)m * 512 + n], v);
        }
    }
}

// ---------------- launch ----------------
extern "C" void kernel_launch(void* const* d_in, const int* in_sizes, int n_in,
                              void* d_out, int out_size) {
    const float* nodes = (const float*)d_in[0];
    const void*  ei    = d_in[1];
    const float* W1    = (const float*)d_in[2];
    const float* b1    = (const float*)d_in[3];
    const float* W2    = (const float*)d_in[4];
    const float* b2    = (const float*)d_in[5];
    const float* W3    = (const float*)d_in[6];
    const float* b3    = (const float*)d_in[7];
    float* out = (float*)d_out;

    k_reset<<<1, 32>>>();
    k_all<<<NBLK, NTHR>>>(nodes, ei, W1, b1, W2, b2,
                          (const float2*)W3, b3, out);
}